// round 15
// baseline (speedup 1.0000x reference)
#include <cuda_runtime.h>
#include <cuda_fp16.h>
#include <math_constants.h>
#include <cstdint>

#define NN_NODES 20000
#define EE_EDGES 320000
#define FF 128
#define HH1 3

// ---------------- scratch ----------------
__device__ float g_h2[NN_NODES * FF];
__device__ float g_el1[NN_NODES * 4];
__device__ float g_er1[NN_NODES * 4];
__device__ float g_el2[NN_NODES];
__device__ float g_er2[NN_NODES];
__device__ float g_wproj[1536];     // wl1[384] | wr1[384] | w2l[384] | w2r[384]
__device__ float g_ufuse[904];      // u_l[384] | u_r[384] | bc[128] | c_l | c_r
__device__ int   g_row[NN_NODES + 1];
__device__ int   g_cursor[NN_NODES];
__device__ int   g_srcp[EE_EDGES];
__device__ int   g_bsums[64];
__device__ __align__(16) __half g_a1cat[NN_NODES * 128];            // fp16(x)
__device__ __align__(16) __half g_xagg[(size_t)NN_NODES * 384];     // aggregated x (3 heads)
__device__ __align__(16) __half g_b2f[128 * 384];                   // fused W1@W2, B-layout [j][c]

// ---------------- helpers ----------------
__device__ __forceinline__ uint32_t smem_u32(const void* p) {
    uint32_t a;
    asm("{ .reg .u64 t; cvta.to.shared.u64 t, %1; cvt.u32.u64 %0, t; }" : "=r"(a) : "l"(p));
    return a;
}
#define LDSM_X4(r0, r1, r2, r3, addr) \
    asm volatile("ldmatrix.sync.aligned.m8n8.x4.shared.b16 {%0,%1,%2,%3}, [%4];" \
                 : "=r"(r0), "=r"(r1), "=r"(r2), "=r"(r3) : "r"(addr))

__device__ __forceinline__ void mma16816(float* d, const uint32_t* a, const uint32_t* b) {
    asm volatile(
        "mma.sync.aligned.m16n8k16.row.col.f32.f16.f16.f32 "
        "{%0,%1,%2,%3}, {%4,%5,%6,%7}, {%8,%9}, {%0,%1,%2,%3};"
        : "+f"(d[0]), "+f"(d[1]), "+f"(d[2]), "+f"(d[3])
        : "r"(a[0]), "r"(a[1]), "r"(a[2]), "r"(a[3]), "r"(b[0]), "r"(b[1]));
}
__device__ __forceinline__ void cp16(uint32_t saddr, const void* g, uint32_t sz) {
    asm volatile("cp.async.cg.shared.global [%0], [%1], 16, %2;"
                 :: "r"(saddr), "l"(g), "r"(sz) : "memory");
}
#define CP_COMMIT() asm volatile("cp.async.commit_group;" ::: "memory")
#define CP_WAIT1()  asm volatile("cp.async.wait_group 1;" ::: "memory")

// ---------------- fp16 mma.sync GEMM, 3-stage cp.async ----------------
// C[M,NCOLS](fp32, +bias) = A[M,K] @ B[NCOLS,K]^T
template <int MROWS>
__global__ __launch_bounds__(256) void gemm_mma(const __half* __restrict__ A,
                                                const __half* __restrict__ B, int K,
                                                float* __restrict__ Cf,
                                                const float* __restrict__ bias,
                                                int M, int NCOLS) {
    extern __shared__ __align__(16) uint8_t smem[];
    constexpr int ASTAGE = MROWS * 128;
    constexpr int STAGE = ASTAGE + 16384;
    constexpr int MT = MROWS / 32;
    constexpr int AP = MROWS / 32;
    const int tid = threadIdx.x, lane = tid & 31, wid = tid >> 5;
    const int bm = blockIdx.x, bn = blockIdx.y;
    const int wm = (wid & 1) * (MROWS / 2), wn = (wid >> 1) * 32;
    const uint32_t sbase = smem_u32(smem);

    float acc[MT][4][4];
    #pragma unroll
    for (int i = 0; i < MT; i++)
        #pragma unroll
        for (int j = 0; j < 4; j++)
            #pragma unroll
            for (int q = 0; q < 4; q++) acc[i][j][q] = 0.f;

    const int lrow = ((lane >> 3) & 1) * 8 + (lane & 7);
    const int lch = lane >> 4;

    uint32_t aro[MT], arx[MT], bro[2], brx[2];
    #pragma unroll
    for (int mt = 0; mt < MT; mt++) {
        int r = wm + mt * 16 + lrow;
        aro[mt] = (uint32_t)(r * 128);
        arx[mt] = (uint32_t)(r & 7);
    }
    #pragma unroll
    for (int h = 0; h < 2; h++) {
        int r = wn + h * 16 + lrow;
        bro[h] = (uint32_t)(r * 128);
        brx[h] = (uint32_t)(r & 7);
    }

    int alr[AP], alc[AP];
    uint32_t aso[AP];
    #pragma unroll
    for (int p = 0; p < AP; p++) {
        int g = tid + p * 256;
        alr[p] = g >> 3;
        alc[p] = g & 7;
        aso[p] = (uint32_t)(alr[p] * 128 + ((alc[p] ^ (alr[p] & 7)) << 4));
    }
    int blr[4], blc[4];
    uint32_t bso[4];
    #pragma unroll
    for (int p = 0; p < 4; p++) {
        int g = tid + p * 256;
        blr[p] = g >> 3;
        blc[p] = g & 7;
        bso[p] = (uint32_t)(blr[p] * 128 + ((blc[p] ^ (blr[p] & 7)) << 4));
    }

    auto issue = [&](int stage, int kn) {
        uint32_t sa = sbase + stage * STAGE;
        uint32_t sb = sa + ASTAGE;
        #pragma unroll
        for (int p = 0; p < AP; p++) {
            int gr = bm * MROWS + alr[p];
            cp16(sa + aso[p], A + (size_t)gr * K + kn + alc[p] * 8,
                 (gr < M) ? 16u : 0u);
        }
        #pragma unroll
        for (int p = 0; p < 4; p++)
            cp16(sb + bso[p], B + (size_t)(bn * 128 + blr[p]) * K + kn + blc[p] * 8, 16u);
        CP_COMMIT();
    };

    issue(0, 0);
    if (K > 64) issue(1, 64);
    else CP_COMMIT();

    const int nchunks = K >> 6;
    for (int ck = 0; ck < nchunks; ck++) {
        CP_WAIT1();
        __syncthreads();
        if (ck + 2 < nchunks) issue((ck + 2) % 3, (ck + 2) * 64);
        else CP_COMMIT();
        uint32_t sAb = sbase + (ck % 3) * STAGE;
        uint32_t sBb = sAb + ASTAGE;
        #pragma unroll
        for (int ks = 0; ks < 4; ks++) {
            const uint32_t c = (uint32_t)(ks * 2 + lch);
            uint32_t af[MT][4];
            #pragma unroll
            for (int mt = 0; mt < MT; mt++)
                LDSM_X4(af[mt][0], af[mt][1], af[mt][2], af[mt][3],
                        sAb + aro[mt] + ((c ^ arx[mt]) << 4));
            uint32_t bf[4][2];
            #pragma unroll
            for (int h = 0; h < 2; h++) {
                uint32_t t0, t1, t2, t3;
                LDSM_X4(t0, t1, t2, t3, sBb + bro[h] + ((c ^ brx[h]) << 4));
                bf[h * 2 + 0][0] = t0; bf[h * 2 + 0][1] = t2;
                bf[h * 2 + 1][0] = t1; bf[h * 2 + 1][1] = t3;
            }
            #pragma unroll
            for (int mt = 0; mt < MT; mt++)
                #pragma unroll
                for (int nt = 0; nt < 4; nt++)
                    mma16816(acc[mt][nt], af[mt], bf[nt]);
        }
    }

    #pragma unroll
    for (int mt = 0; mt < MT; mt++) {
        int gr0 = bm * MROWS + wm + mt * 16 + (lane >> 2);
        #pragma unroll
        for (int nt = 0; nt < 4; nt++) {
            int col = wn + nt * 8 + (lane & 3) * 2;
            int gc = bn * 128 + col;
            float b0 = bias[gc], b1v = bias[gc + 1];
            if (gr0 < M)
                *(float2*)(Cf + (size_t)gr0 * NCOLS + gc) =
                    make_float2(acc[mt][nt][0] + b0, acc[mt][nt][1] + b1v);
            if (gr0 + 8 < M)
                *(float2*)(Cf + (size_t)(gr0 + 8) * NCOLS + gc) =
                    make_float2(acc[mt][nt][2] + b0, acc[mt][nt][3] + b1v);
        }
    }
}

// ---------------- fuse_k: Wf_h = W1_h @ W2_h -> fp16 B-layout b2f[j][h*128+m] ----------------
// grid (4, 3): blockIdx.y = head, blockIdx.x = 32-col j-block. 512 threads.
__global__ __launch_bounds__(512) void fuse_k(const float* __restrict__ W1,
                                              const float* __restrict__ W2,
                                              __half* __restrict__ b2f) {
    extern __shared__ float fsm[];
    float* s1w = fsm;                  // [128][129] (m, k) padded
    float* s2w = fsm + 128 * 129;      // [128][33]  (k, jj) padded
    int h = blockIdx.y, jb = blockIdx.x;
    int t = threadIdx.x;
    for (int i = t; i < 128 * 128; i += 512) {
        int m = i >> 7, k = i & 127;
        s1w[m * 129 + k] = W1[m * 384 + h * 128 + k];
    }
    for (int i = t; i < 128 * 32; i += 512) {
        int k = i >> 5, jj = i & 31;
        s2w[k * 33 + jj] = W2[(h * 128 + k) * 128 + jb * 32 + jj];
    }
    __syncthreads();
    int m = t >> 2;
    int jj0 = (t & 3) * 8;
    float acc[8] = {0.f, 0.f, 0.f, 0.f, 0.f, 0.f, 0.f, 0.f};
    for (int k = 0; k < 128; k++) {
        float a = s1w[m * 129 + k];
        #pragma unroll
        for (int q = 0; q < 8; q++) acc[q] += a * s2w[k * 33 + jj0 + q];
    }
    #pragma unroll
    for (int q = 0; q < 8; q++)
        b2f[(size_t)(jb * 32 + jj0 + q) * 384 + h * 128 + m] = __float2half_rn(acc[q]);
}

// ---------------- proj: attention vectors through weights ----------------
__global__ void proj_k(const float* __restrict__ W1, const float* __restrict__ W2,
                       const float* __restrict__ al1, const float* __restrict__ ar1,
                       const float* __restrict__ al2, const float* __restrict__ ar2,
                       float* __restrict__ wp) {
    int g = blockIdx.x * blockDim.x + threadIdx.x;
    int w = g >> 5, lane = g & 31;
    if (w >= 1536) return;
    const float* vec;
    const float* att;
    if (w < 768) {
        int j = (w < 384) ? w : w - 384;
        int h = j >> 7, k = j & 127;
        vec = W1 + k * 384 + h * 128;
        att = ((w < 384) ? al1 : ar1) + h * 128;
    } else {
        int k = (w < 1152) ? (w - 768) : (w - 1152);
        vec = W2 + k * 128;
        att = (w < 1152) ? al2 : ar2;
    }
    float4 a = *(const float4*)(vec + lane * 4);
    float4 b = *(const float4*)(att + lane * 4);
    float s = a.x * b.x + a.y * b.y + a.z * b.z + a.w * b.w;
    #pragma unroll
    for (int o = 16; o; o >>= 1) s += __shfl_xor_sync(0xffffffffu, s, o);
    if (lane == 0) wp[w] = s;
}

// ---------------- fuse2: u_l/u_r = W1@w2l/r per head, bc = bias1@W2, c_l/c_r ----------------
__global__ void fuse2_k(const float* __restrict__ W1, const float* __restrict__ W2,
                        const float* __restrict__ bias1, const float* __restrict__ wp,
                        float* __restrict__ uf) {
    int g = blockIdx.x * blockDim.x + threadIdx.x;
    int w = g >> 5, lane = g & 31;
    if (w >= 898) return;
    if (w < 768) {
        int c = (w < 384) ? w : w - 384;
        int h = c >> 7, m = c & 127;
        const float* wrow = W1 + m * 384 + h * 128;
        const float* wl = wp + ((w < 384) ? 768 : 1152) + h * 128;
        float4 a = *(const float4*)(wrow + lane * 4);
        float4 b = *(const float4*)(wl + lane * 4);
        float s = a.x * b.x + a.y * b.y + a.z * b.z + a.w * b.w;
        #pragma unroll
        for (int o = 16; o; o >>= 1) s += __shfl_xor_sync(0xffffffffu, s, o);
        if (lane == 0) uf[w] = s;
    } else if (w < 896) {
        int j = w - 768;
        float s = 0.f;
        for (int c = lane; c < 384; c += 32) s += bias1[c] * W2[c * 128 + j];
        #pragma unroll
        for (int o = 16; o; o >>= 1) s += __shfl_xor_sync(0xffffffffu, s, o);
        if (lane == 0) uf[w] = s;
    } else {
        const float* wl = wp + ((w == 896) ? 768 : 1152);
        float s = 0.f;
        for (int c = lane; c < 384; c += 32) s += bias1[c] * wl[c];
        #pragma unroll
        for (int o = 16; o; o >>= 1) s += __shfl_xor_sync(0xffffffffu, s, o);
        if (lane == 0) uf[w] = s;
    }
}

// ---------------- score1 + fp16 conversion of x ----------------
__global__ void score1_k(const float* __restrict__ feats, const float* __restrict__ wp,
                         float* __restrict__ el, float* __restrict__ er,
                         __half* __restrict__ a1) {
    int n = (blockIdx.x * blockDim.x + threadIdx.x) >> 5;
    int lane = threadIdx.x & 31;
    if (n >= NN_NODES) return;
    float4 x = *(const float4*)(feats + (size_t)n * 128 + lane * 4);
    __half2 p0 = __floats2half2_rn(x.x, x.y);
    __half2 p1 = __floats2half2_rn(x.z, x.w);
    uint2 pack;
    pack.x = *(uint32_t*)&p0;
    pack.y = *(uint32_t*)&p1;
    *(uint2*)(a1 + (size_t)n * 128 + lane * 4) = pack;

    float sl[3], sr[3];
    #pragma unroll
    for (int h = 0; h < 3; h++) {
        float4 a = *(const float4*)(wp + h * 128 + lane * 4);
        float4 b = *(const float4*)(wp + 384 + h * 128 + lane * 4);
        sl[h] = x.x * a.x + x.y * a.y + x.z * a.z + x.w * a.w;
        sr[h] = x.x * b.x + x.y * b.y + x.z * b.z + x.w * b.w;
    }
    #pragma unroll
    for (int h = 0; h < 3; h++)
        #pragma unroll
        for (int o = 16; o; o >>= 1) {
            sl[h] += __shfl_xor_sync(0xffffffffu, sl[h], o);
            sr[h] += __shfl_xor_sync(0xffffffffu, sr[h], o);
        }
    if (lane == 0) {
        #pragma unroll
        for (int h = 0; h < 3; h++) {
            el[n * 4 + h] = sl[h];
            er[n * 4 + h] = sr[h];
        }
    }
}

// ---------------- CSR build (4-edge ILP atomics) ----------------
__global__ void count_k(const int* __restrict__ dst, int* row) {
    int base = (blockIdx.x * blockDim.x + threadIdx.x) * 4;
    if (base >= EE_EDGES) return;
    int4 d = *(const int4*)(dst + base);   // E divisible by 4
    atomicAdd(&row[d.x], 1);
    atomicAdd(&row[d.y], 1);
    atomicAdd(&row[d.z], 1);
    atomicAdd(&row[d.w], 1);
}
__global__ void scan_block_k(int* __restrict__ row, int* __restrict__ bsums, int n) {
    __shared__ int sm[512];
    int i = blockIdx.x * 512 + threadIdx.x;
    int v = (i < n) ? row[i] : 0;
    sm[threadIdx.x] = v;
    __syncthreads();
    #pragma unroll
    for (int off = 1; off < 512; off <<= 1) {
        int t = (threadIdx.x >= off) ? sm[threadIdx.x - off] : 0;
        __syncthreads();
        sm[threadIdx.x] += t;
        __syncthreads();
    }
    int incl = sm[threadIdx.x];
    if (i < n) row[i] = incl - v;
    if (threadIdx.x == 511) bsums[blockIdx.x] = incl;
}
__global__ void scan_add_k(int* __restrict__ row, const int* __restrict__ bsums,
                           int* __restrict__ cursor, int n, int nb) {
    __shared__ int sb[65];
    int tid = threadIdx.x;
    if (tid == 0) sb[0] = 0;
    if (tid < 64) {
        int v = (tid < nb) ? bsums[tid] : 0;
        int lane = tid & 31;
        #pragma unroll
        for (int o = 1; o < 32; o <<= 1) {
            int t = __shfl_up_sync(0xffffffffu, v, o);
            if (lane >= o) v += t;
        }
        sb[tid + 1] = v;
    }
    __syncthreads();
    if (tid >= 32 && tid < 64) sb[tid + 1] += sb[32];
    __syncthreads();
    int i = blockIdx.x * blockDim.x + tid;
    if (i < n) {
        int v = row[i] + sb[i >> 9];
        row[i] = v;
        cursor[i] = v;
    }
    if (i == 0) row[n] = EE_EDGES;
}
__global__ void scatter_k(const int* __restrict__ src, const int* __restrict__ dst,
                          int* cursor, int* __restrict__ srcp) {
    int base = (blockIdx.x * blockDim.x + threadIdx.x) * 4;
    if (base >= EE_EDGES) return;
    int4 d = *(const int4*)(dst + base);
    int4 s = *(const int4*)(src + base);
    int p0 = atomicAdd(&cursor[d.x], 1);
    int p1 = atomicAdd(&cursor[d.y], 1);
    int p2 = atomicAdd(&cursor[d.z], 1);
    int p3 = atomicAdd(&cursor[d.w], 1);
    srcp[p0] = s.x;
    srcp[p1] = s.y;
    srcp[p2] = s.z;
    srcp[p3] = s.w;
}

// ---------------- agg1: aggregate fp16 x (3 heads) + fused el2/er2; warp per dst ----------------
__global__ void agg1_k(const __half* __restrict__ x, const float* __restrict__ el,
                       const float* __restrict__ er, const int* __restrict__ row,
                       const int* __restrict__ srcp, const float* __restrict__ uf,
                       __half* __restrict__ xagg,
                       float* __restrict__ el2, float* __restrict__ er2) {
    int d = (blockIdx.x * blockDim.x + threadIdx.x) >> 5;
    int lane = threadIdx.x & 31;
    if (d >= NN_NODES) return;
    int s0 = row[d], s1 = row[d + 1];
    float4 erv = *(const float4*)(er + d * 4);

    float4 acc[3];
    float den[3];
    #pragma unroll
    for (int h = 0; h < 3; h++) {
        acc[h] = make_float4(0.f, 0.f, 0.f, 0.f);
        den[h] = 0.f;
    }
    for (int i = s0; i < s1; ++i) {
        int s = srcp[i];
        float4 elv = *(const float4*)(el + s * 4);
        uint2 raw = *(const uint2*)(x + (size_t)s * 128 + lane * 4);
        float2 v0 = __half22float2(*(__half2*)&raw.x);
        float2 v1 = __half22float2(*(__half2*)&raw.y);
        float e0 = elv.x + erv.x; e0 = (e0 > 0.f) ? e0 : 0.2f * e0;
        float e1 = elv.y + erv.y; e1 = (e1 > 0.f) ? e1 : 0.2f * e1;
        float e2 = elv.z + erv.z; e2 = (e2 > 0.f) ? e2 : 0.2f * e2;
        float w0 = __expf(e0), w1 = __expf(e1), w2 = __expf(e2);
        den[0] += w0; den[1] += w1; den[2] += w2;
        acc[0].x += w0 * v0.x; acc[0].y += w0 * v0.y; acc[0].z += w0 * v1.x; acc[0].w += w0 * v1.y;
        acc[1].x += w1 * v0.x; acc[1].y += w1 * v0.y; acc[1].z += w1 * v1.x; acc[1].w += w1 * v1.y;
        acc[2].x += w2 * v0.x; acc[2].y += w2 * v0.y; acc[2].z += w2 * v1.x; acc[2].w += w2 * v1.y;
    }
    float sl2 = 0.f, sr2 = 0.f;
    #pragma unroll
    for (int h = 0; h < 3; h++) {
        float inv = 1.0f / den[h];
        __half2 o0 = __floats2half2_rn(acc[h].x * inv, acc[h].y * inv);
        __half2 o1 = __floats2half2_rn(acc[h].z * inv, acc[h].w * inv);
        uint2 pack;
        pack.x = *(uint32_t*)&o0;
        pack.y = *(uint32_t*)&o1;
        *(uint2*)(xagg + (size_t)d * 384 + h * 128 + lane * 4) = pack;
        // fused layer-2 scores from the (rounded) aggregated features
        float2 r0 = __half22float2(o0);
        float2 r1 = __half22float2(o1);
        float4 ul = *(const float4*)(uf + h * 128 + lane * 4);
        float4 ur = *(const float4*)(uf + 384 + h * 128 + lane * 4);
        sl2 += r0.x * ul.x + r0.y * ul.y + r1.x * ul.z + r1.y * ul.w;
        sr2 += r0.x * ur.x + r0.y * ur.y + r1.x * ur.z + r1.y * ur.w;
    }
    #pragma unroll
    for (int o = 16; o; o >>= 1) {
        sl2 += __shfl_xor_sync(0xffffffffu, sl2, o);
        sr2 += __shfl_xor_sync(0xffffffffu, sr2, o);
    }
    if (lane == 0) {
        el2[d] = sl2 + uf[896];
        er2[d] = sr2 + uf[897];
    }
}

// ---------------- agg2: gather fp32 h2, +bias2; warp per dst ----------------
__global__ void agg2_k(const float* __restrict__ hfeat, const float* __restrict__ el,
                       const float* __restrict__ er, const float* __restrict__ bias,
                       const int* __restrict__ row, const int* __restrict__ srcp,
                       float* __restrict__ out) {
    int d = (blockIdx.x * blockDim.x + threadIdx.x) >> 5;
    int lane = threadIdx.x & 31;
    if (d >= NN_NODES) return;
    int s0 = row[d], s1 = row[d + 1];
    float erd = er[d];

    float4 acc = make_float4(0.f, 0.f, 0.f, 0.f);
    float den = 0.f;
    #pragma unroll 2
    for (int i = s0; i < s1; ++i) {
        int s = srcp[i];
        float e = el[s] + erd;
        e = (e > 0.f) ? e : 0.2f * e;
        float wt = __expf(e);
        den += wt;
        float4 v = *(const float4*)(hfeat + (size_t)s * 128 + lane * 4);
        acc.x += wt * v.x;
        acc.y += wt * v.y;
        acc.z += wt * v.z;
        acc.w += wt * v.w;
    }
    float inv = 1.0f / den;
    float4 b4 = *(const float4*)(bias + lane * 4);
    *(float4*)(out + (size_t)d * 128 + lane * 4) =
        make_float4(acc.x * inv + b4.x, acc.y * inv + b4.y,
                    acc.z * inv + b4.z, acc.w * inv + b4.w);
}

// ---------------- launch ----------------
static inline int cdiv(int a, int b) { return (a + b - 1) / b; }

extern "C" void kernel_launch(void* const* d_in, const int* in_sizes, int n_in,
                              void* d_out, int out_size) {
    const float* feats   = (const float*)d_in[0];
    const float* W1      = (const float*)d_in[1];
    const float* attn_l1 = (const float*)d_in[2];
    const float* attn_r1 = (const float*)d_in[3];
    const float* bias1   = (const float*)d_in[4];
    const float* W2      = (const float*)d_in[5];
    const float* attn_l2 = (const float*)d_in[6];
    const float* attn_r2 = (const float*)d_in[7];
    const float* bias2   = (const float*)d_in[8];
    const int*   src     = (const int*)d_in[9];
    const int*   dst     = (const int*)d_in[10];
    float* out = (float*)d_out;

    float *h2, *el1, *er1, *el2, *er2, *wp, *uf;
    int *row, *cursor, *srcp, *bsums;
    __half *a1cat, *xagg, *b2f;
    cudaGetSymbolAddress((void**)&h2, g_h2);
    cudaGetSymbolAddress((void**)&el1, g_el1);
    cudaGetSymbolAddress((void**)&er1, g_er1);
    cudaGetSymbolAddress((void**)&el2, g_el2);
    cudaGetSymbolAddress((void**)&er2, g_er2);
    cudaGetSymbolAddress((void**)&wp, g_wproj);
    cudaGetSymbolAddress((void**)&uf, g_ufuse);
    cudaGetSymbolAddress((void**)&row, g_row);
    cudaGetSymbolAddress((void**)&cursor, g_cursor);
    cudaGetSymbolAddress((void**)&srcp, g_srcp);
    cudaGetSymbolAddress((void**)&bsums, g_bsums);
    cudaGetSymbolAddress((void**)&a1cat, g_a1cat);
    cudaGetSymbolAddress((void**)&xagg, g_xagg);
    cudaGetSymbolAddress((void**)&b2f, g_b2f);

    static cudaStream_t s2 = nullptr;
    static cudaEvent_t evFork = nullptr, evJoin = nullptr;
    static bool attrDone = false;
    if (!s2) {
        cudaStreamCreateWithFlags(&s2, cudaStreamNonBlocking);
        cudaEventCreateWithFlags(&evFork, cudaEventDisableTiming);
        cudaEventCreateWithFlags(&evJoin, cudaEventDisableTiming);
    }
    if (!attrDone) {
        cudaFuncSetAttribute(gemm_mma<64>, cudaFuncAttributeMaxDynamicSharedMemorySize,
                             3 * (64 * 128 + 16384));
        cudaFuncSetAttribute(fuse_k, cudaFuncAttributeMaxDynamicSharedMemorySize,
                             (128 * 129 + 128 * 33) * 4);
        attrDone = true;
    }

    const int nb = cdiv(NN_NODES, 512);
    const int fuseSmem = (128 * 129 + 128 * 33) * 4;

    // fork: CSR build on side stream
    cudaEventRecord(evFork, 0);
    cudaStreamWaitEvent(s2, evFork, 0);
    cudaMemsetAsync(row, 0, (NN_NODES + 1) * sizeof(int), s2);
    count_k<<<cdiv(EE_EDGES / 4, 256), 256, 0, s2>>>(dst, row);
    scan_block_k<<<nb, 512, 0, s2>>>(row, bsums, NN_NODES);
    scan_add_k<<<cdiv(NN_NODES, 256), 256, 0, s2>>>(row, bsums, cursor, NN_NODES, nb);
    scatter_k<<<cdiv(EE_EDGES / 4, 256), 256, 0, s2>>>(src, dst, cursor, srcp);
    cudaEventRecord(evJoin, s2);

    // main: fused-weight precompute + projections + layer-1 scores (all hidden under CSR)
    {
        dim3 grid(4, 3);
        fuse_k<<<grid, 512, fuseSmem>>>(W1, W2, b2f);
    }
    proj_k<<<cdiv(1536 * 32, 256), 256>>>(W1, W2, attn_l1, attn_r1, attn_l2, attn_r2, wp);
    fuse2_k<<<cdiv(898 * 32, 256), 256>>>(W1, W2, bias1, wp, uf);
    score1_k<<<cdiv(NN_NODES * 32, 256), 256>>>(feats, wp, el1, er1, a1cat);

    // join: aggregate x (3 heads) + fused layer-2 scores
    cudaStreamWaitEvent(0, evJoin, 0);
    agg1_k<<<cdiv(NN_NODES * 32, 256), 256>>>(a1cat, el1, er1, row, srcp, uf,
                                              xagg, el2, er2);

    // single fused GEMM: h2 = xagg @ Wf + bc
    {
        dim3 grid(cdiv(NN_NODES, 64), 1);
        gemm_mma<64><<<grid, 256, 3 * (64 * 128 + 16384)>>>(
            xagg, b2f, 384, h2, uf + 768, NN_NODES, 128);
    }
    agg2_k<<<cdiv(NN_NODES * 32, 256), 256>>>(h2, el2, er2, bias2, row, srcp, out);
}

// round 16
// speedup vs baseline: 1.1127x; 1.1127x over previous
#include <cuda_runtime.h>
#include <cuda_fp16.h>
#include <math_constants.h>
#include <cstdint>

#define NN_NODES 20000
#define EE_EDGES 320000
#define FF 128
#define HH1 3

// ---------------- scratch ----------------
__device__ float g_h2[NN_NODES * FF];
__device__ float g_el1[NN_NODES * 4];
__device__ float g_er1[NN_NODES * 4];
__device__ float g_el2[NN_NODES];
__device__ float g_er2[NN_NODES];
__device__ float g_wproj[1536];     // wl1[384] | wr1[384] | w2l[384] | w2r[384]
__device__ float g_ufuse[904];      // u_l[384] | u_r[384] | bc[128] | c_l | c_r
__device__ int   g_row[NN_NODES + 1];
__device__ int   g_cursor[NN_NODES];
__device__ int   g_srcp[EE_EDGES];
__device__ int   g_bsums[64];
__device__ __align__(16) __half g_a1cat[NN_NODES * 128];            // fp16(x)
__device__ __align__(16) __half g_xagg[(size_t)NN_NODES * 384];     // aggregated x (3 heads)
__device__ __align__(16) __half g_b2f[128 * 384];                   // fused W1@W2, B-layout

// ---------------- helpers ----------------
__device__ __forceinline__ uint32_t smem_u32(const void* p) {
    uint32_t a;
    asm("{ .reg .u64 t; cvta.to.shared.u64 t, %1; cvt.u32.u64 %0, t; }" : "=r"(a) : "l"(p));
    return a;
}
#define LDSM_X4(r0, r1, r2, r3, addr) \
    asm volatile("ldmatrix.sync.aligned.m8n8.x4.shared.b16 {%0,%1,%2,%3}, [%4];" \
                 : "=r"(r0), "=r"(r1), "=r"(r2), "=r"(r3) : "r"(addr))

__device__ __forceinline__ void mma16816(float* d, const uint32_t* a, const uint32_t* b) {
    asm volatile(
        "mma.sync.aligned.m16n8k16.row.col.f32.f16.f16.f32 "
        "{%0,%1,%2,%3}, {%4,%5,%6,%7}, {%8,%9}, {%0,%1,%2,%3};"
        : "+f"(d[0]), "+f"(d[1]), "+f"(d[2]), "+f"(d[3])
        : "r"(a[0]), "r"(a[1]), "r"(a[2]), "r"(a[3]), "r"(b[0]), "r"(b[1]));
}
__device__ __forceinline__ void cp16(uint32_t saddr, const void* g, uint32_t sz) {
    asm volatile("cp.async.cg.shared.global [%0], [%1], 16, %2;"
                 :: "r"(saddr), "l"(g), "r"(sz) : "memory");
}
#define CP_COMMIT() asm volatile("cp.async.commit_group;" ::: "memory")
#define CP_WAIT1()  asm volatile("cp.async.wait_group 1;" ::: "memory")

// ---------------- fp16 mma.sync GEMM, 3-stage cp.async ----------------
// C[M,NCOLS](fp32, +bias) = A[M,K] @ B[NCOLS,K]^T
template <int MROWS>
__global__ __launch_bounds__(256) void gemm_mma(const __half* __restrict__ A,
                                                const __half* __restrict__ B, int K,
                                                float* __restrict__ Cf,
                                                const float* __restrict__ bias,
                                                int M, int NCOLS) {
    extern __shared__ __align__(16) uint8_t smem[];
    constexpr int ASTAGE = MROWS * 128;
    constexpr int STAGE = ASTAGE + 16384;
    constexpr int MT = MROWS / 32;
    constexpr int AP = MROWS / 32;
    const int tid = threadIdx.x, lane = tid & 31, wid = tid >> 5;
    const int bm = blockIdx.x, bn = blockIdx.y;
    const int wm = (wid & 1) * (MROWS / 2), wn = (wid >> 1) * 32;
    const uint32_t sbase = smem_u32(smem);

    float acc[MT][4][4];
    #pragma unroll
    for (int i = 0; i < MT; i++)
        #pragma unroll
        for (int j = 0; j < 4; j++)
            #pragma unroll
            for (int q = 0; q < 4; q++) acc[i][j][q] = 0.f;

    const int lrow = ((lane >> 3) & 1) * 8 + (lane & 7);
    const int lch = lane >> 4;

    uint32_t aro[MT], arx[MT], bro[2], brx[2];
    #pragma unroll
    for (int mt = 0; mt < MT; mt++) {
        int r = wm + mt * 16 + lrow;
        aro[mt] = (uint32_t)(r * 128);
        arx[mt] = (uint32_t)(r & 7);
    }
    #pragma unroll
    for (int h = 0; h < 2; h++) {
        int r = wn + h * 16 + lrow;
        bro[h] = (uint32_t)(r * 128);
        brx[h] = (uint32_t)(r & 7);
    }

    int alr[AP], alc[AP];
    uint32_t aso[AP];
    #pragma unroll
    for (int p = 0; p < AP; p++) {
        int g = tid + p * 256;
        alr[p] = g >> 3;
        alc[p] = g & 7;
        aso[p] = (uint32_t)(alr[p] * 128 + ((alc[p] ^ (alr[p] & 7)) << 4));
    }
    int blr[4], blc[4];
    uint32_t bso[4];
    #pragma unroll
    for (int p = 0; p < 4; p++) {
        int g = tid + p * 256;
        blr[p] = g >> 3;
        blc[p] = g & 7;
        bso[p] = (uint32_t)(blr[p] * 128 + ((blc[p] ^ (blr[p] & 7)) << 4));
    }

    auto issue = [&](int stage, int kn) {
        uint32_t sa = sbase + stage * STAGE;
        uint32_t sb = sa + ASTAGE;
        #pragma unroll
        for (int p = 0; p < AP; p++) {
            int gr = bm * MROWS + alr[p];
            cp16(sa + aso[p], A + (size_t)gr * K + kn + alc[p] * 8,
                 (gr < M) ? 16u : 0u);
        }
        #pragma unroll
        for (int p = 0; p < 4; p++)
            cp16(sb + bso[p], B + (size_t)(bn * 128 + blr[p]) * K + kn + blc[p] * 8, 16u);
        CP_COMMIT();
    };

    issue(0, 0);
    if (K > 64) issue(1, 64);
    else CP_COMMIT();

    const int nchunks = K >> 6;
    for (int ck = 0; ck < nchunks; ck++) {
        CP_WAIT1();
        __syncthreads();
        if (ck + 2 < nchunks) issue((ck + 2) % 3, (ck + 2) * 64);
        else CP_COMMIT();
        uint32_t sAb = sbase + (ck % 3) * STAGE;
        uint32_t sBb = sAb + ASTAGE;
        #pragma unroll
        for (int ks = 0; ks < 4; ks++) {
            const uint32_t c = (uint32_t)(ks * 2 + lch);
            uint32_t af[MT][4];
            #pragma unroll
            for (int mt = 0; mt < MT; mt++)
                LDSM_X4(af[mt][0], af[mt][1], af[mt][2], af[mt][3],
                        sAb + aro[mt] + ((c ^ arx[mt]) << 4));
            uint32_t bf[4][2];
            #pragma unroll
            for (int h = 0; h < 2; h++) {
                uint32_t t0, t1, t2, t3;
                LDSM_X4(t0, t1, t2, t3, sBb + bro[h] + ((c ^ brx[h]) << 4));
                bf[h * 2 + 0][0] = t0; bf[h * 2 + 0][1] = t2;
                bf[h * 2 + 1][0] = t1; bf[h * 2 + 1][1] = t3;
            }
            #pragma unroll
            for (int mt = 0; mt < MT; mt++)
                #pragma unroll
                for (int nt = 0; nt < 4; nt++)
                    mma16816(acc[mt][nt], af[mt], bf[nt]);
        }
    }

    #pragma unroll
    for (int mt = 0; mt < MT; mt++) {
        int gr0 = bm * MROWS + wm + mt * 16 + (lane >> 2);
        #pragma unroll
        for (int nt = 0; nt < 4; nt++) {
            int col = wn + nt * 8 + (lane & 3) * 2;
            int gc = bn * 128 + col;
            float b0 = bias[gc], b1v = bias[gc + 1];
            if (gr0 < M)
                *(float2*)(Cf + (size_t)gr0 * NCOLS + gc) =
                    make_float2(acc[mt][nt][0] + b0, acc[mt][nt][1] + b1v);
            if (gr0 + 8 < M)
                *(float2*)(Cf + (size_t)(gr0 + 8) * NCOLS + gc) =
                    make_float2(acc[mt][nt][2] + b0, acc[mt][nt][3] + b1v);
        }
    }
}

// ---------------- fuse_k: Wf_h = W1_h @ W2_h -> fp16 B-layout b2f[j][h*128+m] ----------------
__global__ __launch_bounds__(512) void fuse_k(const float* __restrict__ W1,
                                              const float* __restrict__ W2,
                                              __half* __restrict__ b2f) {
    extern __shared__ float fsm[];
    float* s1w = fsm;                  // [128][129]
    float* s2w = fsm + 128 * 129;      // [128][33]
    int h = blockIdx.y, jb = blockIdx.x;
    int t = threadIdx.x;
    for (int i = t; i < 128 * 128; i += 512) {
        int m = i >> 7, k = i & 127;
        s1w[m * 129 + k] = W1[m * 384 + h * 128 + k];
    }
    for (int i = t; i < 128 * 32; i += 512) {
        int k = i >> 5, jj = i & 31;
        s2w[k * 33 + jj] = W2[(h * 128 + k) * 128 + jb * 32 + jj];
    }
    __syncthreads();
    int m = t >> 2;
    int jj0 = (t & 3) * 8;
    float acc[8] = {0.f, 0.f, 0.f, 0.f, 0.f, 0.f, 0.f, 0.f};
    for (int k = 0; k < 128; k++) {
        float a = s1w[m * 129 + k];
        #pragma unroll
        for (int q = 0; q < 8; q++) acc[q] += a * s2w[k * 33 + jj0 + q];
    }
    #pragma unroll
    for (int q = 0; q < 8; q++)
        b2f[(size_t)(jb * 32 + jj0 + q) * 384 + h * 128 + m] = __float2half_rn(acc[q]);
}

// ---------------- proj: attention vectors through weights ----------------
__global__ void proj_k(const float* __restrict__ W1, const float* __restrict__ W2,
                       const float* __restrict__ al1, const float* __restrict__ ar1,
                       const float* __restrict__ al2, const float* __restrict__ ar2,
                       float* __restrict__ wp) {
    int g = blockIdx.x * blockDim.x + threadIdx.x;
    int w = g >> 5, lane = g & 31;
    if (w >= 1536) return;
    const float* vec;
    const float* att;
    if (w < 768) {
        int j = (w < 384) ? w : w - 384;
        int h = j >> 7, k = j & 127;
        vec = W1 + k * 384 + h * 128;
        att = ((w < 384) ? al1 : ar1) + h * 128;
    } else {
        int k = (w < 1152) ? (w - 768) : (w - 1152);
        vec = W2 + k * 128;
        att = (w < 1152) ? al2 : ar2;
    }
    float4 a = *(const float4*)(vec + lane * 4);
    float4 b = *(const float4*)(att + lane * 4);
    float s = a.x * b.x + a.y * b.y + a.z * b.z + a.w * b.w;
    #pragma unroll
    for (int o = 16; o; o >>= 1) s += __shfl_xor_sync(0xffffffffu, s, o);
    if (lane == 0) wp[w] = s;
}

// ---------------- fuse2: u_l/u_r = W1@w2l/r per head, bc = bias1@W2, c_l/c_r ----------------
__global__ void fuse2_k(const float* __restrict__ W1, const float* __restrict__ W2,
                        const float* __restrict__ bias1, const float* __restrict__ wp,
                        float* __restrict__ uf) {
    int g = blockIdx.x * blockDim.x + threadIdx.x;
    int w = g >> 5, lane = g & 31;
    if (w >= 898) return;
    if (w < 768) {
        int c = (w < 384) ? w : w - 384;
        int h = c >> 7, m = c & 127;
        const float* wrow = W1 + m * 384 + h * 128;
        const float* wl = wp + ((w < 384) ? 768 : 1152) + h * 128;
        float4 a = *(const float4*)(wrow + lane * 4);
        float4 b = *(const float4*)(wl + lane * 4);
        float s = a.x * b.x + a.y * b.y + a.z * b.z + a.w * b.w;
        #pragma unroll
        for (int o = 16; o; o >>= 1) s += __shfl_xor_sync(0xffffffffu, s, o);
        if (lane == 0) uf[w] = s;
    } else if (w < 896) {
        int j = w - 768;
        float s = 0.f;
        for (int c = lane; c < 384; c += 32) s += bias1[c] * W2[c * 128 + j];
        #pragma unroll
        for (int o = 16; o; o >>= 1) s += __shfl_xor_sync(0xffffffffu, s, o);
        if (lane == 0) uf[w] = s;
    } else {
        const float* wl = wp + ((w == 896) ? 768 : 1152);
        float s = 0.f;
        for (int c = lane; c < 384; c += 32) s += bias1[c] * wl[c];
        #pragma unroll
        for (int o = 16; o; o >>= 1) s += __shfl_xor_sync(0xffffffffu, s, o);
        if (lane == 0) uf[w] = s;
    }
}

// ---------------- score1 + fp16 conversion of x ----------------
__global__ void score1_k(const float* __restrict__ feats, const float* __restrict__ wp,
                         float* __restrict__ el, float* __restrict__ er,
                         __half* __restrict__ a1) {
    int n = (blockIdx.x * blockDim.x + threadIdx.x) >> 5;
    int lane = threadIdx.x & 31;
    if (n >= NN_NODES) return;
    float4 x = *(const float4*)(feats + (size_t)n * 128 + lane * 4);
    __half2 p0 = __floats2half2_rn(x.x, x.y);
    __half2 p1 = __floats2half2_rn(x.z, x.w);
    uint2 pack;
    pack.x = *(uint32_t*)&p0;
    pack.y = *(uint32_t*)&p1;
    *(uint2*)(a1 + (size_t)n * 128 + lane * 4) = pack;

    float sl[3], sr[3];
    #pragma unroll
    for (int h = 0; h < 3; h++) {
        float4 a = *(const float4*)(wp + h * 128 + lane * 4);
        float4 b = *(const float4*)(wp + 384 + h * 128 + lane * 4);
        sl[h] = x.x * a.x + x.y * a.y + x.z * a.z + x.w * a.w;
        sr[h] = x.x * b.x + x.y * b.y + x.z * b.z + x.w * b.w;
    }
    #pragma unroll
    for (int h = 0; h < 3; h++)
        #pragma unroll
        for (int o = 16; o; o >>= 1) {
            sl[h] += __shfl_xor_sync(0xffffffffu, sl[h], o);
            sr[h] += __shfl_xor_sync(0xffffffffu, sr[h], o);
        }
    if (lane == 0) {
        #pragma unroll
        for (int h = 0; h < 3; h++) {
            el[n * 4 + h] = sl[h];
            er[n * 4 + h] = sr[h];
        }
    }
}

// ---------------- score2x: el2/er2 from aggregated xagg via fused u vectors ----------------
__global__ void score2x_k(const __half* __restrict__ xagg, const float* __restrict__ uf,
                          float* __restrict__ el2, float* __restrict__ er2) {
    int n = (blockIdx.x * blockDim.x + threadIdx.x) >> 5;
    int lane = threadIdx.x & 31;
    if (n >= NN_NODES) return;
    float sl = 0.f, sr = 0.f;
    #pragma unroll
    for (int seg = 0; seg < 3; seg++) {
        int k0 = seg * 128 + lane * 4;
        uint2 raw = *(const uint2*)(xagg + (size_t)n * 384 + k0);
        float2 v0 = __half22float2(*(__half2*)&raw.x);
        float2 v1 = __half22float2(*(__half2*)&raw.y);
        float4 a = *(const float4*)(uf + k0);
        float4 b = *(const float4*)(uf + 384 + k0);
        sl += v0.x * a.x + v0.y * a.y + v1.x * a.z + v1.y * a.w;
        sr += v0.x * b.x + v0.y * b.y + v1.x * b.z + v1.y * b.w;
    }
    #pragma unroll
    for (int o = 16; o; o >>= 1) {
        sl += __shfl_xor_sync(0xffffffffu, sl, o);
        sr += __shfl_xor_sync(0xffffffffu, sr, o);
    }
    if (lane == 0) {
        el2[n] = sl + uf[896];
        er2[n] = sr + uf[897];
    }
}

// ---------------- CSR build ----------------
__global__ void count_k(const int* __restrict__ dst, int* row) {
    int e = blockIdx.x * blockDim.x + threadIdx.x;
    if (e < EE_EDGES) atomicAdd(&row[dst[e]], 1);
}
// single-kernel decoupled-lookback scan (40 blocks, all co-resident on 148 SMs)
__global__ void scan_fused_k(int* __restrict__ row, int* __restrict__ cursor,
                             int* __restrict__ bsums, int n) {
    __shared__ int sm[512];
    __shared__ int exc;
    int tid = threadIdx.x;
    int i = blockIdx.x * 512 + tid;
    int v = (i < n) ? row[i] : 0;
    sm[tid] = v;
    __syncthreads();
    #pragma unroll
    for (int off = 1; off < 512; off <<= 1) {
        int t = (tid >= off) ? sm[tid - off] : 0;
        __syncthreads();
        sm[tid] += t;
        __syncthreads();
    }
    int incl = sm[tid];
    if (tid == 0) exc = 0;
    if (tid == 511) atomicExch(&bsums[blockIdx.x], sm[511] + 1);  // flag: total+1 (nonzero)
    __syncthreads();
    if (tid < blockIdx.x) {  // poll one predecessor each (blockIdx < 40 < 512)
        int val;
        do { val = atomicAdd(&bsums[tid], 0); } while (val == 0);
        atomicAdd(&exc, val - 1);
    }
    __syncthreads();
    int base = exc;
    if (i < n) {
        int o = base + incl - v;
        row[i] = o;
        cursor[i] = o;
    }
    if (i == 0) row[n] = EE_EDGES;
}
__global__ void scatter_k(const int* __restrict__ src, const int* __restrict__ dst,
                          int* cursor, int* __restrict__ srcp) {
    int e = blockIdx.x * blockDim.x + threadIdx.x;
    if (e < EE_EDGES) {
        int p = atomicAdd(&cursor[dst[e]], 1);
        srcp[p] = src[e];
    }
}

// ---------------- agg1: aggregate 128-dim fp16 x for all 3 heads; warp per dst ----------------
__global__ void agg1_k(const __half* __restrict__ x, const float* __restrict__ el,
                       const float* __restrict__ er, const int* __restrict__ row,
                       const int* __restrict__ srcp, __half* __restrict__ xagg) {
    int d = (blockIdx.x * blockDim.x + threadIdx.x) >> 5;
    int lane = threadIdx.x & 31;
    if (d >= NN_NODES) return;
    int s0 = row[d], s1 = row[d + 1];
    float4 erv = *(const float4*)(er + d * 4);

    float4 acc[3];
    float den[3];
    #pragma unroll
    for (int h = 0; h < 3; h++) {
        acc[h] = make_float4(0.f, 0.f, 0.f, 0.f);
        den[h] = 0.f;
    }
    for (int i = s0; i < s1; ++i) {
        int s = srcp[i];
        float4 elv = *(const float4*)(el + s * 4);
        uint2 raw = *(const uint2*)(x + (size_t)s * 128 + lane * 4);
        float2 v0 = __half22float2(*(__half2*)&raw.x);
        float2 v1 = __half22float2(*(__half2*)&raw.y);
        float e0 = elv.x + erv.x; e0 = (e0 > 0.f) ? e0 : 0.2f * e0;
        float e1 = elv.y + erv.y; e1 = (e1 > 0.f) ? e1 : 0.2f * e1;
        float e2 = elv.z + erv.z; e2 = (e2 > 0.f) ? e2 : 0.2f * e2;
        float w0 = __expf(e0), w1 = __expf(e1), w2 = __expf(e2);
        den[0] += w0; den[1] += w1; den[2] += w2;
        acc[0].x += w0 * v0.x; acc[0].y += w0 * v0.y; acc[0].z += w0 * v1.x; acc[0].w += w0 * v1.y;
        acc[1].x += w1 * v0.x; acc[1].y += w1 * v0.y; acc[1].z += w1 * v1.x; acc[1].w += w1 * v1.y;
        acc[2].x += w2 * v0.x; acc[2].y += w2 * v0.y; acc[2].z += w2 * v1.x; acc[2].w += w2 * v1.y;
    }
    #pragma unroll
    for (int h = 0; h < 3; h++) {
        float inv = 1.0f / den[h];
        __half2 o0 = __floats2half2_rn(acc[h].x * inv, acc[h].y * inv);
        __half2 o1 = __floats2half2_rn(acc[h].z * inv, acc[h].w * inv);
        uint2 pack;
        pack.x = *(uint32_t*)&o0;
        pack.y = *(uint32_t*)&o1;
        *(uint2*)(xagg + (size_t)d * 384 + h * 128 + lane * 4) = pack;
    }
}

// ---------------- agg2: gather fp32 h2, +bias2; warp per dst ----------------
__global__ void agg2_k(const float* __restrict__ hfeat, const float* __restrict__ el,
                       const float* __restrict__ er, const float* __restrict__ bias,
                       const int* __restrict__ row, const int* __restrict__ srcp,
                       float* __restrict__ out) {
    int d = (blockIdx.x * blockDim.x + threadIdx.x) >> 5;
    int lane = threadIdx.x & 31;
    if (d >= NN_NODES) return;
    int s0 = row[d], s1 = row[d + 1];
    float erd = er[d];

    float4 acc = make_float4(0.f, 0.f, 0.f, 0.f);
    float den = 0.f;
    #pragma unroll 2
    for (int i = s0; i < s1; ++i) {
        int s = srcp[i];
        float e = el[s] + erd;
        e = (e > 0.f) ? e : 0.2f * e;
        float wt = __expf(e);
        den += wt;
        float4 v = *(const float4*)(hfeat + (size_t)s * 128 + lane * 4);
        acc.x += wt * v.x;
        acc.y += wt * v.y;
        acc.z += wt * v.z;
        acc.w += wt * v.w;
    }
    float inv = 1.0f / den;
    float4 b4 = *(const float4*)(bias + lane * 4);
    *(float4*)(out + (size_t)d * 128 + lane * 4) =
        make_float4(acc.x * inv + b4.x, acc.y * inv + b4.y,
                    acc.z * inv + b4.z, acc.w * inv + b4.w);
}

// ---------------- launch ----------------
static inline int cdiv(int a, int b) { return (a + b - 1) / b; }

extern "C" void kernel_launch(void* const* d_in, const int* in_sizes, int n_in,
                              void* d_out, int out_size) {
    const float* feats   = (const float*)d_in[0];
    const float* W1      = (const float*)d_in[1];
    const float* attn_l1 = (const float*)d_in[2];
    const float* attn_r1 = (const float*)d_in[3];
    const float* bias1   = (const float*)d_in[4];
    const float* W2      = (const float*)d_in[5];
    const float* attn_l2 = (const float*)d_in[6];
    const float* attn_r2 = (const float*)d_in[7];
    const float* bias2   = (const float*)d_in[8];
    const int*   src     = (const int*)d_in[9];
    const int*   dst     = (const int*)d_in[10];
    float* out = (float*)d_out;

    float *h2, *el1, *er1, *el2, *er2, *wp, *uf;
    int *row, *cursor, *srcp, *bsums;
    __half *a1cat, *xagg, *b2f;
    cudaGetSymbolAddress((void**)&h2, g_h2);
    cudaGetSymbolAddress((void**)&el1, g_el1);
    cudaGetSymbolAddress((void**)&er1, g_er1);
    cudaGetSymbolAddress((void**)&el2, g_el2);
    cudaGetSymbolAddress((void**)&er2, g_er2);
    cudaGetSymbolAddress((void**)&wp, g_wproj);
    cudaGetSymbolAddress((void**)&uf, g_ufuse);
    cudaGetSymbolAddress((void**)&row, g_row);
    cudaGetSymbolAddress((void**)&cursor, g_cursor);
    cudaGetSymbolAddress((void**)&srcp, g_srcp);
    cudaGetSymbolAddress((void**)&bsums, g_bsums);
    cudaGetSymbolAddress((void**)&a1cat, g_a1cat);
    cudaGetSymbolAddress((void**)&xagg, g_xagg);
    cudaGetSymbolAddress((void**)&b2f, g_b2f);

    static cudaStream_t s2 = nullptr;
    static cudaEvent_t evFork = nullptr, evJoin = nullptr, evA1 = nullptr, evS2 = nullptr;
    static bool attrDone = false;
    if (!s2) {
        cudaStreamCreateWithFlags(&s2, cudaStreamNonBlocking);
        cudaEventCreateWithFlags(&evFork, cudaEventDisableTiming);
        cudaEventCreateWithFlags(&evJoin, cudaEventDisableTiming);
        cudaEventCreateWithFlags(&evA1, cudaEventDisableTiming);
        cudaEventCreateWithFlags(&evS2, cudaEventDisableTiming);
    }
    if (!attrDone) {
        cudaFuncSetAttribute(gemm_mma<64>, cudaFuncAttributeMaxDynamicSharedMemorySize,
                             3 * (64 * 128 + 16384));
        cudaFuncSetAttribute(fuse_k, cudaFuncAttributeMaxDynamicSharedMemorySize,
                             (128 * 129 + 128 * 33) * 4);
        attrDone = true;
    }

    const int nb = cdiv(NN_NODES, 512);  // 40 blocks
    const int fuseSmem = (128 * 129 + 128 * 33) * 4;

    // fork: CSR build on side stream (memset x2 + 3 kernels)
    cudaEventRecord(evFork, 0);
    cudaStreamWaitEvent(s2, evFork, 0);
    cudaMemsetAsync(row, 0, (NN_NODES + 1) * sizeof(int), s2);
    cudaMemsetAsync(bsums, 0, 64 * sizeof(int), s2);
    count_k<<<cdiv(EE_EDGES, 256), 256, 0, s2>>>(dst, row);
    scan_fused_k<<<nb, 512, 0, s2>>>(row, cursor, bsums, NN_NODES);
    scatter_k<<<cdiv(EE_EDGES, 256), 256, 0, s2>>>(src, dst, cursor, srcp);
    cudaEventRecord(evJoin, s2);

    // main: fused-weight precompute + projections + layer-1 scores (hidden under CSR)
    {
        dim3 grid(4, 3);
        fuse_k<<<grid, 512, fuseSmem>>>(W1, W2, b2f);
    }
    proj_k<<<cdiv(1536 * 32, 256), 256>>>(W1, W2, attn_l1, attn_r1, attn_l2, attn_r2, wp);
    fuse2_k<<<cdiv(898 * 32, 256), 256>>>(W1, W2, bias1, wp, uf);
    score1_k<<<cdiv(NN_NODES * 32, 256), 256>>>(feats, wp, el1, er1, a1cat);

    // join: aggregate x per head (R14-style agg1, untouched)
    cudaStreamWaitEvent(0, evJoin, 0);
    agg1_k<<<cdiv(NN_NODES * 32, 256), 256>>>(a1cat, el1, er1, row, srcp, xagg);
    cudaEventRecord(evA1, 0);

    // side stream: layer-2 scores from xagg, concurrent with fused GEMM
    cudaStreamWaitEvent(s2, evA1, 0);
    score2x_k<<<cdiv(NN_NODES * 32, 256), 256, 0, s2>>>(xagg, uf, el2, er2);
    cudaEventRecord(evS2, s2);

    // main: single fused GEMM h2 = xagg @ Wf + bc
    {
        dim3 grid(cdiv(NN_NODES, 64), 1);
        gemm_mma<64><<<grid, 256, 3 * (64 * 128 + 16384)>>>(
            xagg, b2f, 384, h2, uf + 768, NN_NODES, 128);
    }
    cudaStreamWaitEvent(0, evS2, 0);
    agg2_k<<<cdiv(NN_NODES * 32, 256), 256>>>(h2, el2, er2, bias2, row, srcp, out);
}

// round 17
// speedup vs baseline: 1.2130x; 1.0901x over previous
#include <cuda_runtime.h>
#include <cuda_fp16.h>
#include <math_constants.h>
#include <cstdint>

#define NN_NODES 20000
#define EE_EDGES 320000
#define FF 128
#define HH1 3

// ---------------- scratch ----------------
__device__ float g_h2[NN_NODES * FF];
__device__ float g_el1[NN_NODES * 4];
__device__ float g_er1[NN_NODES * 4];
__device__ float g_el2[NN_NODES];
__device__ float g_er2[NN_NODES];
__device__ float g_wproj[1536];     // wl1[384] | wr1[384] | w2l[384] | w2r[384]
__device__ float g_ufuse[904];      // u_l[384] | u_r[384] | bc[128] | c_l | c_r
__device__ int   g_row[NN_NODES + 1];
__device__ int   g_cursor[NN_NODES];
__device__ int   g_srcp[EE_EDGES];
__device__ int   g_bsums[64];
__device__ __align__(16) __half g_a1cat[NN_NODES * 128];            // fp16(x)
__device__ __align__(16) __half g_xagg[(size_t)NN_NODES * 384];     // aggregated x (3 heads)
__device__ __align__(16) __half g_b2f[128 * 384];                   // fused W1@W2, B-layout

// ---------------- helpers ----------------
__device__ __forceinline__ uint32_t smem_u32(const void* p) {
    uint32_t a;
    asm("{ .reg .u64 t; cvta.to.shared.u64 t, %1; cvt.u32.u64 %0, t; }" : "=r"(a) : "l"(p));
    return a;
}
#define LDSM_X4(r0, r1, r2, r3, addr) \
    asm volatile("ldmatrix.sync.aligned.m8n8.x4.shared.b16 {%0,%1,%2,%3}, [%4];" \
                 : "=r"(r0), "=r"(r1), "=r"(r2), "=r"(r3) : "r"(addr))

__device__ __forceinline__ void mma16816(float* d, const uint32_t* a, const uint32_t* b) {
    asm volatile(
        "mma.sync.aligned.m16n8k16.row.col.f32.f16.f16.f32 "
        "{%0,%1,%2,%3}, {%4,%5,%6,%7}, {%8,%9}, {%0,%1,%2,%3};"
        : "+f"(d[0]), "+f"(d[1]), "+f"(d[2]), "+f"(d[3])
        : "r"(a[0]), "r"(a[1]), "r"(a[2]), "r"(a[3]), "r"(b[0]), "r"(b[1]));
}
__device__ __forceinline__ void cp16(uint32_t saddr, const void* g, uint32_t sz) {
    asm volatile("cp.async.cg.shared.global [%0], [%1], 16, %2;"
                 :: "r"(saddr), "l"(g), "r"(sz) : "memory");
}
#define CP_COMMIT() asm volatile("cp.async.commit_group;" ::: "memory")
#define CP_WAIT1()  asm volatile("cp.async.wait_group 1;" ::: "memory")

// ---------------- fp16 mma.sync GEMM, 3-stage cp.async ----------------
// C[M,NCOLS](fp32, +bias) = A[M,K] @ B[NCOLS,K]^T
template <int MROWS>
__global__ __launch_bounds__(256) void gemm_mma(const __half* __restrict__ A,
                                                const __half* __restrict__ B, int K,
                                                float* __restrict__ Cf,
                                                const float* __restrict__ bias,
                                                int M, int NCOLS) {
    extern __shared__ __align__(16) uint8_t smem[];
    constexpr int ASTAGE = MROWS * 128;
    constexpr int STAGE = ASTAGE + 16384;
    constexpr int MT = MROWS / 32;
    constexpr int AP = MROWS / 32;
    const int tid = threadIdx.x, lane = tid & 31, wid = tid >> 5;
    const int bm = blockIdx.x, bn = blockIdx.y;
    const int wm = (wid & 1) * (MROWS / 2), wn = (wid >> 1) * 32;
    const uint32_t sbase = smem_u32(smem);

    float acc[MT][4][4];
    #pragma unroll
    for (int i = 0; i < MT; i++)
        #pragma unroll
        for (int j = 0; j < 4; j++)
            #pragma unroll
            for (int q = 0; q < 4; q++) acc[i][j][q] = 0.f;

    const int lrow = ((lane >> 3) & 1) * 8 + (lane & 7);
    const int lch = lane >> 4;

    uint32_t aro[MT], arx[MT], bro[2], brx[2];
    #pragma unroll
    for (int mt = 0; mt < MT; mt++) {
        int r = wm + mt * 16 + lrow;
        aro[mt] = (uint32_t)(r * 128);
        arx[mt] = (uint32_t)(r & 7);
    }
    #pragma unroll
    for (int h = 0; h < 2; h++) {
        int r = wn + h * 16 + lrow;
        bro[h] = (uint32_t)(r * 128);
        brx[h] = (uint32_t)(r & 7);
    }

    int alr[AP], alc[AP];
    uint32_t aso[AP];
    #pragma unroll
    for (int p = 0; p < AP; p++) {
        int g = tid + p * 256;
        alr[p] = g >> 3;
        alc[p] = g & 7;
        aso[p] = (uint32_t)(alr[p] * 128 + ((alc[p] ^ (alr[p] & 7)) << 4));
    }
    int blr[4], blc[4];
    uint32_t bso[4];
    #pragma unroll
    for (int p = 0; p < 4; p++) {
        int g = tid + p * 256;
        blr[p] = g >> 3;
        blc[p] = g & 7;
        bso[p] = (uint32_t)(blr[p] * 128 + ((blc[p] ^ (blr[p] & 7)) << 4));
    }

    auto issue = [&](int stage, int kn) {
        uint32_t sa = sbase + stage * STAGE;
        uint32_t sb = sa + ASTAGE;
        #pragma unroll
        for (int p = 0; p < AP; p++) {
            int gr = bm * MROWS + alr[p];
            cp16(sa + aso[p], A + (size_t)gr * K + kn + alc[p] * 8,
                 (gr < M) ? 16u : 0u);
        }
        #pragma unroll
        for (int p = 0; p < 4; p++)
            cp16(sb + bso[p], B + (size_t)(bn * 128 + blr[p]) * K + kn + blc[p] * 8, 16u);
        CP_COMMIT();
    };

    issue(0, 0);
    if (K > 64) issue(1, 64);
    else CP_COMMIT();

    const int nchunks = K >> 6;
    for (int ck = 0; ck < nchunks; ck++) {
        CP_WAIT1();
        __syncthreads();
        if (ck + 2 < nchunks) issue((ck + 2) % 3, (ck + 2) * 64);
        else CP_COMMIT();
        uint32_t sAb = sbase + (ck % 3) * STAGE;
        uint32_t sBb = sAb + ASTAGE;
        #pragma unroll
        for (int ks = 0; ks < 4; ks++) {
            const uint32_t c = (uint32_t)(ks * 2 + lch);
            uint32_t af[MT][4];
            #pragma unroll
            for (int mt = 0; mt < MT; mt++)
                LDSM_X4(af[mt][0], af[mt][1], af[mt][2], af[mt][3],
                        sAb + aro[mt] + ((c ^ arx[mt]) << 4));
            uint32_t bf[4][2];
            #pragma unroll
            for (int h = 0; h < 2; h++) {
                uint32_t t0, t1, t2, t3;
                LDSM_X4(t0, t1, t2, t3, sBb + bro[h] + ((c ^ brx[h]) << 4));
                bf[h * 2 + 0][0] = t0; bf[h * 2 + 0][1] = t2;
                bf[h * 2 + 1][0] = t1; bf[h * 2 + 1][1] = t3;
            }
            #pragma unroll
            for (int mt = 0; mt < MT; mt++)
                #pragma unroll
                for (int nt = 0; nt < 4; nt++)
                    mma16816(acc[mt][nt], af[mt], bf[nt]);
        }
    }

    #pragma unroll
    for (int mt = 0; mt < MT; mt++) {
        int gr0 = bm * MROWS + wm + mt * 16 + (lane >> 2);
        #pragma unroll
        for (int nt = 0; nt < 4; nt++) {
            int col = wn + nt * 8 + (lane & 3) * 2;
            int gc = bn * 128 + col;
            float b0 = bias[gc], b1v = bias[gc + 1];
            if (gr0 < M)
                *(float2*)(Cf + (size_t)gr0 * NCOLS + gc) =
                    make_float2(acc[mt][nt][0] + b0, acc[mt][nt][1] + b1v);
            if (gr0 + 8 < M)
                *(float2*)(Cf + (size_t)(gr0 + 8) * NCOLS + gc) =
                    make_float2(acc[mt][nt][2] + b0, acc[mt][nt][3] + b1v);
        }
    }
}

// ---------------- fuse_k: Wf_h = W1_h @ W2_h -> fp16 B-layout b2f[j][h*128+m] ----------------
__global__ __launch_bounds__(512) void fuse_k(const float* __restrict__ W1,
                                              const float* __restrict__ W2,
                                              __half* __restrict__ b2f) {
    extern __shared__ float fsm[];
    float* s1w = fsm;                  // [128][129]
    float* s2w = fsm + 128 * 129;      // [128][33]
    int h = blockIdx.y, jb = blockIdx.x;
    int t = threadIdx.x;
    for (int i = t; i < 128 * 128; i += 512) {
        int m = i >> 7, k = i & 127;
        s1w[m * 129 + k] = W1[m * 384 + h * 128 + k];
    }
    for (int i = t; i < 128 * 32; i += 512) {
        int k = i >> 5, jj = i & 31;
        s2w[k * 33 + jj] = W2[(h * 128 + k) * 128 + jb * 32 + jj];
    }
    __syncthreads();
    int m = t >> 2;
    int jj0 = (t & 3) * 8;
    float acc[8] = {0.f, 0.f, 0.f, 0.f, 0.f, 0.f, 0.f, 0.f};
    #pragma unroll 4
    for (int k = 0; k < 128; k++) {
        float a = s1w[m * 129 + k];
        #pragma unroll
        for (int q = 0; q < 8; q++) acc[q] += a * s2w[k * 33 + jj0 + q];
    }
    #pragma unroll
    for (int q = 0; q < 8; q++)
        b2f[(size_t)(jb * 32 + jj0 + q) * 384 + h * 128 + m] = __float2half_rn(acc[q]);
}

// ---------------- proj: attention vectors through weights ----------------
__global__ void proj_k(const float* __restrict__ W1, const float* __restrict__ W2,
                       const float* __restrict__ al1, const float* __restrict__ ar1,
                       const float* __restrict__ al2, const float* __restrict__ ar2,
                       float* __restrict__ wp) {
    int g = blockIdx.x * blockDim.x + threadIdx.x;
    int w = g >> 5, lane = g & 31;
    if (w >= 1536) return;
    const float* vec;
    const float* att;
    if (w < 768) {
        int j = (w < 384) ? w : w - 384;
        int h = j >> 7, k = j & 127;
        vec = W1 + k * 384 + h * 128;
        att = ((w < 384) ? al1 : ar1) + h * 128;
    } else {
        int k = (w < 1152) ? (w - 768) : (w - 1152);
        vec = W2 + k * 128;
        att = (w < 1152) ? al2 : ar2;
    }
    float4 a = *(const float4*)(vec + lane * 4);
    float4 b = *(const float4*)(att + lane * 4);
    float s = a.x * b.x + a.y * b.y + a.z * b.z + a.w * b.w;
    #pragma unroll
    for (int o = 16; o; o >>= 1) s += __shfl_xor_sync(0xffffffffu, s, o);
    if (lane == 0) wp[w] = s;
}

// ---------------- fuse2: u_l/u_r = W1@w2l/r per head, bc = bias1@W2, c_l/c_r ----------------
__global__ void fuse2_k(const float* __restrict__ W1, const float* __restrict__ W2,
                        const float* __restrict__ bias1, const float* __restrict__ wp,
                        float* __restrict__ uf) {
    int g = blockIdx.x * blockDim.x + threadIdx.x;
    int w = g >> 5, lane = g & 31;
    if (w >= 898) return;
    if (w < 768) {
        int c = (w < 384) ? w : w - 384;
        int h = c >> 7, m = c & 127;
        const float* wrow = W1 + m * 384 + h * 128;
        const float* wl = wp + ((w < 384) ? 768 : 1152) + h * 128;
        float4 a = *(const float4*)(wrow + lane * 4);
        float4 b = *(const float4*)(wl + lane * 4);
        float s = a.x * b.x + a.y * b.y + a.z * b.z + a.w * b.w;
        #pragma unroll
        for (int o = 16; o; o >>= 1) s += __shfl_xor_sync(0xffffffffu, s, o);
        if (lane == 0) uf[w] = s;
    } else if (w < 896) {
        int j = w - 768;
        float s = 0.f;
        for (int c = lane; c < 384; c += 32) s += bias1[c] * W2[c * 128 + j];
        #pragma unroll
        for (int o = 16; o; o >>= 1) s += __shfl_xor_sync(0xffffffffu, s, o);
        if (lane == 0) uf[w] = s;
    } else {
        const float* wl = wp + ((w == 896) ? 768 : 1152);
        float s = 0.f;
        for (int c = lane; c < 384; c += 32) s += bias1[c] * wl[c];
        #pragma unroll
        for (int o = 16; o; o >>= 1) s += __shfl_xor_sync(0xffffffffu, s, o);
        if (lane == 0) uf[w] = s;
    }
}

// ---------------- score1 + fp16 conversion of x ----------------
__global__ void score1_k(const float* __restrict__ feats, const float* __restrict__ wp,
                         float* __restrict__ el, float* __restrict__ er,
                         __half* __restrict__ a1) {
    int n = (blockIdx.x * blockDim.x + threadIdx.x) >> 5;
    int lane = threadIdx.x & 31;
    if (n >= NN_NODES) return;
    float4 x = *(const float4*)(feats + (size_t)n * 128 + lane * 4);
    __half2 p0 = __floats2half2_rn(x.x, x.y);
    __half2 p1 = __floats2half2_rn(x.z, x.w);
    uint2 pack;
    pack.x = *(uint32_t*)&p0;
    pack.y = *(uint32_t*)&p1;
    *(uint2*)(a1 + (size_t)n * 128 + lane * 4) = pack;

    float sl[3], sr[3];
    #pragma unroll
    for (int h = 0; h < 3; h++) {
        float4 a = *(const float4*)(wp + h * 128 + lane * 4);
        float4 b = *(const float4*)(wp + 384 + h * 128 + lane * 4);
        sl[h] = x.x * a.x + x.y * a.y + x.z * a.z + x.w * a.w;
        sr[h] = x.x * b.x + x.y * b.y + x.z * b.z + x.w * b.w;
    }
    #pragma unroll
    for (int h = 0; h < 3; h++)
        #pragma unroll
        for (int o = 16; o; o >>= 1) {
            sl[h] += __shfl_xor_sync(0xffffffffu, sl[h], o);
            sr[h] += __shfl_xor_sync(0xffffffffu, sr[h], o);
        }
    if (lane == 0) {
        #pragma unroll
        for (int h = 0; h < 3; h++) {
            el[n * 4 + h] = sl[h];
            er[n * 4 + h] = sr[h];
        }
    }
}

// ---------------- score2x: el2/er2 from aggregated xagg via fused u vectors ----------------
__global__ void score2x_k(const __half* __restrict__ xagg, const float* __restrict__ uf,
                          float* __restrict__ el2, float* __restrict__ er2) {
    int n = (blockIdx.x * blockDim.x + threadIdx.x) >> 5;
    int lane = threadIdx.x & 31;
    if (n >= NN_NODES) return;
    float sl = 0.f, sr = 0.f;
    #pragma unroll
    for (int seg = 0; seg < 3; seg++) {
        int k0 = seg * 128 + lane * 4;
        uint2 raw = *(const uint2*)(xagg + (size_t)n * 384 + k0);
        float2 v0 = __half22float2(*(__half2*)&raw.x);
        float2 v1 = __half22float2(*(__half2*)&raw.y);
        float4 a = *(const float4*)(uf + k0);
        float4 b = *(const float4*)(uf + 384 + k0);
        sl += v0.x * a.x + v0.y * a.y + v1.x * a.z + v1.y * a.w;
        sr += v0.x * b.x + v0.y * b.y + v1.x * b.z + v1.y * b.w;
    }
    #pragma unroll
    for (int o = 16; o; o >>= 1) {
        sl += __shfl_xor_sync(0xffffffffu, sl, o);
        sr += __shfl_xor_sync(0xffffffffu, sr, o);
    }
    if (lane == 0) {
        el2[n] = sl + uf[896];
        er2[n] = sr + uf[897];
    }
}

// ---------------- CSR build ----------------
__global__ void count_k(const int* __restrict__ dst, int* row) {
    int e = blockIdx.x * blockDim.x + threadIdx.x;
    if (e < EE_EDGES) atomicAdd(&row[dst[e]], 1);
}
__global__ void scan_fused_k(int* __restrict__ row, int* __restrict__ cursor,
                             int* __restrict__ bsums, int n) {
    __shared__ int sm[512];
    __shared__ int exc;
    int tid = threadIdx.x;
    int i = blockIdx.x * 512 + tid;
    int v = (i < n) ? row[i] : 0;
    sm[tid] = v;
    __syncthreads();
    #pragma unroll
    for (int off = 1; off < 512; off <<= 1) {
        int t = (tid >= off) ? sm[tid - off] : 0;
        __syncthreads();
        sm[tid] += t;
        __syncthreads();
    }
    int incl = sm[tid];
    if (tid == 0) exc = 0;
    if (tid == 511) atomicExch(&bsums[blockIdx.x], sm[511] + 1);
    __syncthreads();
    if (tid < blockIdx.x) {
        int val;
        do { val = atomicAdd(&bsums[tid], 0); } while (val == 0);
        atomicAdd(&exc, val - 1);
    }
    __syncthreads();
    int base = exc;
    if (i < n) {
        int o = base + incl - v;
        row[i] = o;
        cursor[i] = o;
    }
    if (i == 0) row[n] = EE_EDGES;
}
__global__ void scatter_k(const int* __restrict__ src, const int* __restrict__ dst,
                          int* cursor, int* __restrict__ srcp) {
    int e = blockIdx.x * blockDim.x + threadIdx.x;
    if (e < EE_EDGES) {
        int p = atomicAdd(&cursor[dst[e]], 1);
        srcp[p] = src[e];
    }
}

// ---------------- agg1: aggregate 128-dim fp16 x for all 3 heads; warp per dst ----------------
__global__ void agg1_k(const __half* __restrict__ x, const float* __restrict__ el,
                       const float* __restrict__ er, const int* __restrict__ row,
                       const int* __restrict__ srcp, __half* __restrict__ xagg) {
    int d = (blockIdx.x * blockDim.x + threadIdx.x) >> 5;
    int lane = threadIdx.x & 31;
    if (d >= NN_NODES) return;
    int s0 = row[d], s1 = row[d + 1];
    float4 erv = *(const float4*)(er + d * 4);

    float4 acc[3];
    float den[3];
    #pragma unroll
    for (int h = 0; h < 3; h++) {
        acc[h] = make_float4(0.f, 0.f, 0.f, 0.f);
        den[h] = 0.f;
    }
    for (int i = s0; i < s1; ++i) {
        int s = srcp[i];
        float4 elv = *(const float4*)(el + s * 4);
        uint2 raw = *(const uint2*)(x + (size_t)s * 128 + lane * 4);
        float2 v0 = __half22float2(*(__half2*)&raw.x);
        float2 v1 = __half22float2(*(__half2*)&raw.y);
        float e0 = elv.x + erv.x; e0 = (e0 > 0.f) ? e0 : 0.2f * e0;
        float e1 = elv.y + erv.y; e1 = (e1 > 0.f) ? e1 : 0.2f * e1;
        float e2 = elv.z + erv.z; e2 = (e2 > 0.f) ? e2 : 0.2f * e2;
        float w0 = __expf(e0), w1 = __expf(e1), w2 = __expf(e2);
        den[0] += w0; den[1] += w1; den[2] += w2;
        acc[0].x += w0 * v0.x; acc[0].y += w0 * v0.y; acc[0].z += w0 * v1.x; acc[0].w += w0 * v1.y;
        acc[1].x += w1 * v0.x; acc[1].y += w1 * v0.y; acc[1].z += w1 * v1.x; acc[1].w += w1 * v1.y;
        acc[2].x += w2 * v0.x; acc[2].y += w2 * v0.y; acc[2].z += w2 * v1.x; acc[2].w += w2 * v1.y;
    }
    #pragma unroll
    for (int h = 0; h < 3; h++) {
        float inv = 1.0f / den[h];
        __half2 o0 = __floats2half2_rn(acc[h].x * inv, acc[h].y * inv);
        __half2 o1 = __floats2half2_rn(acc[h].z * inv, acc[h].w * inv);
        uint2 pack;
        pack.x = *(uint32_t*)&o0;
        pack.y = *(uint32_t*)&o1;
        *(uint2*)(xagg + (size_t)d * 384 + h * 128 + lane * 4) = pack;
    }
}

// ---------------- agg2: gather fp32 h2, +bias2; warp per dst ----------------
__global__ void agg2_k(const float* __restrict__ hfeat, const float* __restrict__ el,
                       const float* __restrict__ er, const float* __restrict__ bias,
                       const int* __restrict__ row, const int* __restrict__ srcp,
                       float* __restrict__ out) {
    int d = (blockIdx.x * blockDim.x + threadIdx.x) >> 5;
    int lane = threadIdx.x & 31;
    if (d >= NN_NODES) return;
    int s0 = row[d], s1 = row[d + 1];
    float erd = er[d];

    float4 acc = make_float4(0.f, 0.f, 0.f, 0.f);
    float den = 0.f;
    #pragma unroll 2
    for (int i = s0; i < s1; ++i) {
        int s = srcp[i];
        float e = el[s] + erd;
        e = (e > 0.f) ? e : 0.2f * e;
        float wt = __expf(e);
        den += wt;
        float4 v = *(const float4*)(hfeat + (size_t)s * 128 + lane * 4);
        acc.x += wt * v.x;
        acc.y += wt * v.y;
        acc.z += wt * v.z;
        acc.w += wt * v.w;
    }
    float inv = 1.0f / den;
    float4 b4 = *(const float4*)(bias + lane * 4);
    *(float4*)(out + (size_t)d * 128 + lane * 4) =
        make_float4(acc.x * inv + b4.x, acc.y * inv + b4.y,
                    acc.z * inv + b4.z, acc.w * inv + b4.w);
}

// ---------------- launch ----------------
static inline int cdiv(int a, int b) { return (a + b - 1) / b; }

extern "C" void kernel_launch(void* const* d_in, const int* in_sizes, int n_in,
                              void* d_out, int out_size) {
    const float* feats   = (const float*)d_in[0];
    const float* W1      = (const float*)d_in[1];
    const float* attn_l1 = (const float*)d_in[2];
    const float* attn_r1 = (const float*)d_in[3];
    const float* bias1   = (const float*)d_in[4];
    const float* W2      = (const float*)d_in[5];
    const float* attn_l2 = (const float*)d_in[6];
    const float* attn_r2 = (const float*)d_in[7];
    const float* bias2   = (const float*)d_in[8];
    const int*   src     = (const int*)d_in[9];
    const int*   dst     = (const int*)d_in[10];
    float* out = (float*)d_out;

    float *h2, *el1, *er1, *el2, *er2, *wp, *uf;
    int *row, *cursor, *srcp, *bsums;
    __half *a1cat, *xagg, *b2f;
    cudaGetSymbolAddress((void**)&h2, g_h2);
    cudaGetSymbolAddress((void**)&el1, g_el1);
    cudaGetSymbolAddress((void**)&er1, g_er1);
    cudaGetSymbolAddress((void**)&el2, g_el2);
    cudaGetSymbolAddress((void**)&er2, g_er2);
    cudaGetSymbolAddress((void**)&wp, g_wproj);
    cudaGetSymbolAddress((void**)&uf, g_ufuse);
    cudaGetSymbolAddress((void**)&row, g_row);
    cudaGetSymbolAddress((void**)&cursor, g_cursor);
    cudaGetSymbolAddress((void**)&srcp, g_srcp);
    cudaGetSymbolAddress((void**)&bsums, g_bsums);
    cudaGetSymbolAddress((void**)&a1cat, g_a1cat);
    cudaGetSymbolAddress((void**)&xagg, g_xagg);
    cudaGetSymbolAddress((void**)&b2f, g_b2f);

    static cudaStream_t s2 = nullptr, s3 = nullptr;
    static cudaEvent_t evFork = nullptr, evJoin = nullptr, evA1 = nullptr,
                       evS2 = nullptr, evProj = nullptr, evFuse = nullptr;
    static bool attrDone = false;
    if (!s2) {
        cudaStreamCreateWithFlags(&s2, cudaStreamNonBlocking);
        cudaStreamCreateWithFlags(&s3, cudaStreamNonBlocking);
        cudaEventCreateWithFlags(&evFork, cudaEventDisableTiming);
        cudaEventCreateWithFlags(&evJoin, cudaEventDisableTiming);
        cudaEventCreateWithFlags(&evA1, cudaEventDisableTiming);
        cudaEventCreateWithFlags(&evS2, cudaEventDisableTiming);
        cudaEventCreateWithFlags(&evProj, cudaEventDisableTiming);
        cudaEventCreateWithFlags(&evFuse, cudaEventDisableTiming);
    }
    if (!attrDone) {
        cudaFuncSetAttribute(gemm_mma<64>, cudaFuncAttributeMaxDynamicSharedMemorySize,
                             3 * (64 * 128 + 16384));
        cudaFuncSetAttribute(fuse_k, cudaFuncAttributeMaxDynamicSharedMemorySize,
                             (128 * 129 + 128 * 33) * 4);
        attrDone = true;
    }

    const int nb = cdiv(NN_NODES, 512);  // 40 blocks
    const int fuseSmem = (128 * 129 + 128 * 33) * 4;

    cudaEventRecord(evFork, 0);

    // s2: CSR build
    cudaStreamWaitEvent(s2, evFork, 0);
    cudaMemsetAsync(row, 0, (NN_NODES + 1) * sizeof(int), s2);
    cudaMemsetAsync(bsums, 0, 64 * sizeof(int), s2);
    count_k<<<cdiv(EE_EDGES, 256), 256, 0, s2>>>(dst, row);
    scan_fused_k<<<nb, 512, 0, s2>>>(row, cursor, bsums, NN_NODES);
    scatter_k<<<cdiv(EE_EDGES, 256), 256, 0, s2>>>(src, dst, cursor, srcp);
    cudaEventRecord(evJoin, s2);

    // s3: fused-weight precompute (off the critical path; hidden under CSR + agg1)
    cudaStreamWaitEvent(s3, evFork, 0);
    {
        dim3 grid(4, 3);
        fuse_k<<<grid, 512, fuseSmem, s3>>>(W1, W2, b2f);
    }

    // main: projections + layer-1 scores (short pre-join path)
    proj_k<<<cdiv(1536 * 32, 256), 256>>>(W1, W2, attn_l1, attn_r1, attn_l2, attn_r2, wp);
    cudaEventRecord(evProj, 0);
    score1_k<<<cdiv(NN_NODES * 32, 256), 256>>>(feats, wp, el1, er1, a1cat);

    // s3: fuse2 needs wp
    cudaStreamWaitEvent(s3, evProj, 0);
    fuse2_k<<<cdiv(898 * 32, 256), 256, 0, s3>>>(W1, W2, bias1, wp, uf);
    cudaEventRecord(evFuse, s3);

    // main: join CSR, aggregate x per head
    cudaStreamWaitEvent(0, evJoin, 0);
    agg1_k<<<cdiv(NN_NODES * 32, 256), 256>>>(a1cat, el1, er1, row, srcp, xagg);
    cudaEventRecord(evA1, 0);

    // s2: layer-2 scores from xagg (needs uf), concurrent with fused GEMM
    cudaStreamWaitEvent(s2, evA1, 0);
    cudaStreamWaitEvent(s2, evFuse, 0);
    score2x_k<<<cdiv(NN_NODES * 32, 256), 256, 0, s2>>>(xagg, uf, el2, er2);
    cudaEventRecord(evS2, s2);

    // main: single fused GEMM h2 = xagg @ Wf + bc (needs b2f + uf)
    cudaStreamWaitEvent(0, evFuse, 0);
    {
        dim3 grid(cdiv(NN_NODES, 64), 1);
        gemm_mma<64><<<grid, 256, 3 * (64 * 128 + 16384)>>>(
            xagg, b2f, 384, h2, uf + 768, NN_NODES, 128);
    }
    cudaStreamWaitEvent(0, evS2, 0);
    agg2_k<<<cdiv(NN_NODES * 32, 256), 256>>>(h2, el2, er2, bias2, row, srcp, out);
}